// round 4
// baseline (speedup 1.0000x reference)
#include <cuda_runtime.h>
#include <cuda_bf16.h>
#include <math.h>
#include <stdint.h>

// ---------------- problem constants ----------------
#define S_LEN 2048
#define BATCH 2
#define NTOK  (S_LEN*BATCH)     // 4096
#define NH    16
#define DIM   2048
#define NOPE  128
#define ROPE  64
#define RHALF 32
#define VDIM  128
#define KVR   512
#define QD    (NOPE+ROPE)       // 192
#define QOUT  (NH*QD)           // 3072
#define KVOUT (KVR+ROPE)        // 576
#define DEFF  576
#define NSTAGE 3

typedef long long ll;
typedef __nv_bfloat16 bf16;
typedef __nv_bfloat162 bf162;

// ---------------- scratch: bf16 hi/lo planes + fp32 scores ----------------
__device__ __align__(16) bf16 g_xs_h [(size_t)NTOK*DIM],    g_xs_l [(size_t)NTOK*DIM];
__device__ __align__(16) bf16 g_wqs_h[(size_t)QOUT*DIM],    g_wqs_l[(size_t)QOUT*DIM];
__device__ __align__(16) bf16 g_was_h[(size_t)KVOUT*DIM],   g_was_l[(size_t)KVOUT*DIM];
__device__ __align__(16) bf16 g_wbs_h[(size_t)NH*(NOPE+VDIM)*KVR], g_wbs_l[(size_t)NH*(NOPE+VDIM)*KVR];
__device__ __align__(16) bf16 g_wbT_h[(size_t)NH*KVR*NOPE], g_wbT_l[(size_t)NH*KVR*NOPE];
__device__ __align__(16) bf16 g_wos_h[(size_t)DIM*NH*VDIM], g_wos_l[(size_t)DIM*NH*VDIM];
__device__ __align__(16) bf16 g_qs_h [(size_t)NTOK*QOUT],   g_qs_l [(size_t)NTOK*QOUT];
__device__ __align__(16) bf16 g_kvs_h[(size_t)NTOK*KVOUT],  g_kvs_l[(size_t)NTOK*KVOUT];
__device__ __align__(16) bf16 g_ke_h [(size_t)NTOK*DEFF],   g_ke_l [(size_t)NTOK*DEFF];
__device__ __align__(16) bf16 g_keT_h[(size_t)BATCH*DEFF*S_LEN], g_keT_l[(size_t)BATCH*DEFF*S_LEN];
__device__ __align__(16) bf16 g_qe_h [(size_t)BATCH*NH*S_LEN*DEFF], g_qe_l [(size_t)BATCH*NH*S_LEN*DEFF];
__device__ float g_scores[(size_t)BATCH*NH*S_LEN*S_LEN];
__device__ __align__(16) bf16 g_pr_h [(size_t)BATCH*NH*S_LEN*S_LEN], g_pr_l [(size_t)BATCH*NH*S_LEN*S_LEN];
__device__ __align__(16) bf16 g_ol_h [(size_t)BATCH*NH*S_LEN*KVR],  g_ol_l [(size_t)BATCH*NH*S_LEN*KVR];
__device__ __align__(16) bf16 g_os_h [(size_t)NTOK*NH*VDIM], g_os_l [(size_t)NTOK*NH*VDIM];
__device__ float g_cos[S_LEN*RHALF];
__device__ float g_sin[S_LEN*RHALF];

// ---------------- helpers ----------------
__device__ __forceinline__ float warpMax(float v){
    #pragma unroll
    for (int o=16;o;o>>=1) v = fmaxf(v, __shfl_xor_sync(0xffffffffu, v, o));
    return v;
}
__device__ __forceinline__ float warpSum(float v){
    #pragma unroll
    for (int o=16;o;o>>=1) v += __shfl_xor_sync(0xffffffffu, v, o);
    return v;
}
__device__ __forceinline__ uint32_t smem_u32(const void* p){
    uint32_t a;
    asm("{ .reg .u64 t; cvta.to.shared.u64 t, %1; cvt.u32.u64 %0, t; }" : "=r"(a) : "l"(p));
    return a;
}
__device__ __forceinline__ void split2(float f, bf16& h, bf16& l){
    h = __float2bfloat16_rn(f);
    l = __float2bfloat16_rn(f - __bfloat162float(h));
}
__device__ __forceinline__ float rejoin(bf16 h, bf16 l){
    return __bfloat162float(h) + __bfloat162float(l);
}
__device__ __forceinline__ void mma_bf16(float* d, const uint32_t* a, const uint32_t* b){
    asm volatile(
        "mma.sync.aligned.m16n8k16.row.col.f32.bf16.bf16.f32 "
        "{%0,%1,%2,%3}, {%4,%5,%6,%7}, {%8,%9}, {%0,%1,%2,%3};"
        : "+f"(d[0]), "+f"(d[1]), "+f"(d[2]), "+f"(d[3])
        : "r"(a[0]), "r"(a[1]), "r"(a[2]), "r"(a[3]), "r"(b[0]), "r"(b[1]));
}
__device__ __forceinline__ void cp16(uint32_t dst, const void* src){
    asm volatile("cp.async.cg.shared.global [%0], [%1], 16;\n" :: "r"(dst), "l"(src) : "memory");
}
__device__ __forceinline__ void cp_commit(){ asm volatile("cp.async.commit_group;\n" ::: "memory"); }
__device__ __forceinline__ void cp_wait1(){ asm volatile("cp.async.wait_group 1;\n" ::: "memory"); }

// SW64-style swizzle for 64B rows (bf16 k32): XOR bits[5:4] with bits[8:7]
__device__ __forceinline__ uint32_t swz(uint32_t o){ return o ^ ((o>>3)&0x30u); }
__device__ __forceinline__ uint32_t lds_sw(uint32_t base, int row, int off){
    uint32_t o = (uint32_t)(row*64 + off);
    o ^= ((o>>3)&0x30u);
    uint32_t v; asm volatile("ld.shared.b32 %0, [%1];" : "=r"(v) : "r"(base + o));
    return v;
}

// ---------------- split kernels ----------------
__global__ void split_arr(const float4* __restrict__ src, bf16* __restrict__ h, bf16* __restrict__ l, int n4){
    int i = blockIdx.x*blockDim.x + threadIdx.x;
    if (i >= n4) return;
    float4 v = src[i];
    bf16 h0,l0,h1,l1,h2,l2,h3,l3;
    split2(v.x,h0,l0); split2(v.y,h1,l1); split2(v.z,h2,l2); split2(v.w,h3,l3);
    bf162* hp = (bf162*)(h + 4*(size_t)i);
    bf162* lp = (bf162*)(l + 4*(size_t)i);
    bf162 a; a.x=h0; a.y=h1; hp[0]=a;
    bf162 b; b.x=h2; b.y=h3; hp[1]=b;
    bf162 c; c.x=l0; c.y=l1; lp[0]=c;
    bf162 d; d.x=l2; d.y=l3; lp[1]=d;
}
// wkv_bT[h][c][d] = wkv_b[h*256 + d][c]  (nope part only)
__global__ void splitT_wkvb(const float* __restrict__ wb){
    int i = blockIdx.x*blockDim.x + threadIdx.x;
    if (i >= NH*KVR*NOPE) return;
    int d = i % NOPE, c = (i/NOPE) % KVR, h = i/(NOPE*KVR);
    float v = wb[((size_t)h*(NOPE+VDIM) + d)*KVR + c];
    split2(v, g_wbT_h[i], g_wbT_l[i]);
}

// ---------------- prep kernels ----------------
__global__ void rope_prep_kernel(const float* __restrict__ ang){
    int i = blockIdx.x*blockDim.x + threadIdx.x;
    if (i < S_LEN*RHALF){
        float a = ang[i];
        g_cos[i] = cosf(a);
        g_sin[i] = sinf(a);
    }
}

__global__ void prep_keff_kernel(const float* __restrict__ kvw){
    int t = blockIdx.x;
    int b = t / S_LEN, s = t % S_LEN;
    int tid = threadIdx.x;
    float v[4];
    #pragma unroll
    for (int j=0;j<4;j++){
        size_t idx = (size_t)t*KVOUT + 4*tid + j;
        v[j] = rejoin(g_kvs_h[idx], g_kvs_l[idx]);
    }
    float ss = v[0]*v[0]+v[1]*v[1]+v[2]*v[2]+v[3]*v[3];
    ss = warpSum(ss);
    __shared__ float red[4];
    if ((tid&31)==0) red[tid>>5] = ss;
    __syncthreads();
    float tot = red[0]+red[1]+red[2]+red[3];
    float r = rsqrtf(tot*(1.0f/KVR) + 1e-6f);
    #pragma unroll
    for (int j=0;j<4;j++){
        int c = 4*tid + j;
        float o = v[j]*r*kvw[c];
        bf16 h,l; split2(o,h,l);
        size_t di = (size_t)t*DEFF + c;
        g_ke_h[di]=h; g_ke_l[di]=l;
        size_t ti = ((size_t)b*DEFF + c)*S_LEN + s;
        g_keT_h[ti]=h; g_keT_l[ti]=l;
    }
    if (tid < RHALF){
        size_t pi = (size_t)t*KVOUT + KVR + 2*tid;
        float xr = rejoin(g_kvs_h[pi],   g_kvs_l[pi]);
        float xi = rejoin(g_kvs_h[pi+1], g_kvs_l[pi+1]);
        float c  = g_cos[s*RHALF+tid], sn = g_sin[s*RHALF+tid];
        float yr = xr*c - xi*sn, yi = xr*sn + xi*c;
        bf16 hr,lr,hi2,li; split2(yr,hr,lr); split2(yi,hi2,li);
        size_t di = (size_t)t*DEFF + KVR + 2*tid;
        g_ke_h[di]=hr; g_ke_l[di]=lr; g_ke_h[di+1]=hi2; g_ke_l[di+1]=li;
        size_t t0 = ((size_t)b*DEFF + KVR + 2*tid)*S_LEN + s;
        size_t t1 = ((size_t)b*DEFF + KVR + 2*tid + 1)*S_LEN + s;
        g_keT_h[t0]=hr; g_keT_l[t0]=lr; g_keT_h[t1]=hi2; g_keT_l[t1]=li;
    }
}

__global__ void prep_qpe_kernel(){
    int t = blockIdx.x, h = blockIdx.y;
    int b = t / S_LEN, s = t % S_LEN;
    int i = threadIdx.x;   // 0..31
    size_t si = (size_t)t*QOUT + h*QD + NOPE + 2*i;
    float xr = rejoin(g_qs_h[si],   g_qs_l[si]);
    float xi = rejoin(g_qs_h[si+1], g_qs_l[si+1]);
    float c  = g_cos[s*RHALF+i], sn = g_sin[s*RHALF+i];
    float yr = xr*c - xi*sn, yi = xr*sn + xi*c;
    size_t di = ((size_t)(b*NH+h)*S_LEN + s)*DEFF + KVR + 2*i;
    bf16 hh,ll_; split2(yr,hh,ll_); g_qe_h[di]=hh;   g_qe_l[di]=ll_;
    split2(yi,hh,ll_);              g_qe_h[di+1]=hh; g_qe_l[di+1]=ll_;
}

// ---------------- bf16x3 split GEMM ----------------
// C = alpha * (Ah+Al)[M,K] @ (Bh+Bl)[N,K]^T   (all operands K-contiguous)
// BM=128, BN=BN_T, BK=32.  SPLIT_OUT: write hi/lo planes, else fp32.
template<int BN_T, bool SPLIT_OUT>
__global__ __launch_bounds__(256,2) void mma_gemm(
    const bf16* __restrict__ Ah, const bf16* __restrict__ Al,
    const bf16* __restrict__ Bh, const bf16* __restrict__ Bl,
    float* __restrict__ Cf, bf16* __restrict__ Ch, bf16* __restrict__ Cl,
    int K, int lda, int ldb, int ldc, int zdiv,
    ll zA1, ll zA2, ll zB1, ll zB2, ll zC1, ll zC2,
    float alpha, int causal, int klimit)
{
    if (causal && blockIdx.x > blockIdx.y) return;
    constexpr int WN  = BN_T/32;
    constexpr int WM  = 8/WN;
    constexpr int WTM = 128/WM;
    constexpr int MF  = WTM/16;
    constexpr int NF  = 4;
    constexpr int SA  = 128*64;        // 8KB per A plane
    constexpr int SB  = BN_T*64;
    constexpr int STG = 2*SA + 2*SB;

    extern __shared__ char smc[];
    const uint32_t sbase = smem_u32(smc);

    const int tid = threadIdx.x, lane = tid & 31, wid = tid >> 5;
    const int wm = wid / WN, wn = wid % WN;
    const int grp = lane >> 2, tig = lane & 3;
    const int zl = blockIdx.z % zdiv, zh = blockIdx.z / zdiv;
    const ll n0 = (ll)blockIdx.x * BN_T;

    const ll aoff = zl*zA1 + zh*zA2 + (ll)blockIdx.y*128*lda;
    const bf16* Ahb = Ah + aoff;
    const bf16* Alb = Al + aoff;
    const ll boff = zl*zB1 + zh*zB2 + n0*ldb;
    const bf16* Bhb = Bh + boff;
    const bf16* Blb = Bl + boff;

    int kEnd = K;
    if (klimit){ int kl = ((int)blockIdx.y + 1)*128; if (kl < kEnd) kEnd = kl; }
    const int nk = kEnd >> 5;

    float acc[MF][NF][4];
    #pragma unroll
    for (int i=0;i<MF;i++)
        #pragma unroll
        for (int j=0;j<NF;j++)
            #pragma unroll
            for (int c=0;c<4;c++) acc[i][j][c] = 0.f;

    const int row = tid >> 2, g = tid & 3;

    auto LOAD = [&](int kb){
        const int s = kb % NSTAGE;
        const uint32_t ub = sbase + (uint32_t)(s*STG);
        const ll koff = ((ll)kb << 5) + g*8;
        #pragma unroll
        for (int i=0;i<2;i++){
            int r = row + i*64;
            uint32_t o = swz((uint32_t)(r*64 + g*16));
            cp16(ub + o,      Ahb + (ll)r*lda + koff);
            cp16(ub + SA + o, Alb + (ll)r*lda + koff);
        }
        #pragma unroll
        for (int i=0;i<BN_T/64;i++){
            int r = row + i*64;
            uint32_t o = swz((uint32_t)(r*64 + g*16));
            cp16(ub + 2*SA + o,      Bhb + (ll)r*ldb + koff);
            cp16(ub + 2*SA + SB + o, Blb + (ll)r*ldb + koff);
        }
        cp_commit();
    };

    #pragma unroll
    for (int kb=0; kb<NSTAGE-1; kb++) if (kb < nk) LOAD(kb);

    for (int k=0; k<nk; k++){
        cp_wait1();
        __syncthreads();
        if (k + NSTAGE - 1 < nk) LOAD(k + NSTAGE - 1);
        else cp_commit();

        const int s = k % NSTAGE;
        const uint32_t AsH = sbase + s*STG + (uint32_t)(wm*WTM*64);
        const uint32_t AsL = AsH + SA;
        const uint32_t BsH = sbase + s*STG + 2*SA + (uint32_t)(wn*32*64);
        const uint32_t BsL = BsH + SB;

        #pragma unroll
        for (int kk=0; kk<2; kk++){
            const int kb = kk*32 + tig*4;
            uint32_t ah[MF][4], bh[NF][2];
            #pragma unroll
            for (int nf=0; nf<NF; nf++){
                bh[nf][0] = lds_sw(BsH, nf*8+grp, kb);
                bh[nf][1] = lds_sw(BsH, nf*8+grp, kb+16);
            }
            #pragma unroll
            for (int mf=0; mf<MF; mf++){
                ah[mf][0] = lds_sw(AsH, mf*16+grp,   kb);
                ah[mf][1] = lds_sw(AsH, mf*16+grp+8, kb);
                ah[mf][2] = lds_sw(AsH, mf*16+grp,   kb+16);
                ah[mf][3] = lds_sw(AsH, mf*16+grp+8, kb+16);
            }
            #pragma unroll
            for (int mf=0; mf<MF; mf++)
                #pragma unroll
                for (int nf=0; nf<NF; nf++)
                    mma_bf16(acc[mf][nf], ah[mf], bh[nf]);

            uint32_t bl[NF][2];
            #pragma unroll
            for (int nf=0; nf<NF; nf++){
                bl[nf][0] = lds_sw(BsL, nf*8+grp, kb);
                bl[nf][1] = lds_sw(BsL, nf*8+grp, kb+16);
            }
            #pragma unroll
            for (int mf=0; mf<MF; mf++)
                #pragma unroll
                for (int nf=0; nf<NF; nf++)
                    mma_bf16(acc[mf][nf], ah[mf], bl[nf]);

            uint32_t al[MF][4];
            #pragma unroll
            for (int mf=0; mf<MF; mf++){
                al[mf][0] = lds_sw(AsL, mf*16+grp,   kb);
                al[mf][1] = lds_sw(AsL, mf*16+grp+8, kb);
                al[mf][2] = lds_sw(AsL, mf*16+grp,   kb+16);
                al[mf][3] = lds_sw(AsL, mf*16+grp+8, kb+16);
            }
            #pragma unroll
            for (int mf=0; mf<MF; mf++)
                #pragma unroll
                for (int nf=0; nf<NF; nf++)
                    mma_bf16(acc[mf][nf], al[mf], bh[nf]);
        }
    }

    // ---- epilogue ----
    const ll cbase = zl*zC1 + zh*zC2
                   + ((ll)blockIdx.y*128 + wm*WTM)*ldc + n0 + wn*32;
    #pragma unroll
    for (int mf=0; mf<MF; mf++){
        int r0 = mf*16 + grp;
        #pragma unroll
        for (int nf=0; nf<NF; nf++){
            int c = nf*8 + tig*2;
            #pragma unroll
            for (int half=0; half<2; half++){
                ll off = cbase + (ll)(r0 + half*8)*ldc + c;
                float v0 = acc[mf][nf][2*half+0]*alpha;
                float v1 = acc[mf][nf][2*half+1]*alpha;
                if (SPLIT_OUT){
                    bf16 h0,l0,h1,l1;
                    split2(v0,h0,l0); split2(v1,h1,l1);
                    bf162 hp; hp.x=h0; hp.y=h1;
                    bf162 lp; lp.x=l0; lp.y=l1;
                    *(bf162*)(Ch + off) = hp;
                    *(bf162*)(Cl + off) = lp;
                } else {
                    float2 o; o.x=v0; o.y=v1;
                    *(float2*)(Cf + off) = o;
                }
            }
        }
    }
}

// ---------------- causal softmax: fp32 scores -> bf16 hi/lo probs ----------------
__global__ void softmax_kernel(){
    const int s = blockIdx.x;
    const ll z = blockIdx.y;
    const float* row = g_scores + (z*S_LEN + (ll)s)*S_LEN;
    bf16* ph = g_pr_h + (z*S_LEN + (ll)s)*S_LEN;
    bf16* pl = g_pr_l + (z*S_LEN + (ll)s)*S_LEN;
    const int n = s + 1;
    const int tid = threadIdx.x;

    float mx = -1e30f;
    for (int t = tid; t < n; t += 128) mx = fmaxf(mx, row[t]);
    mx = warpMax(mx);
    __shared__ float redm[4], reds[4];
    if ((tid&31)==0) redm[tid>>5] = mx;
    __syncthreads();
    mx = fmaxf(fmaxf(redm[0],redm[1]), fmaxf(redm[2],redm[3]));

    float sum = 0.f;
    for (int t = tid; t < n; t += 128) sum += __expf(row[t] - mx);
    sum = warpSum(sum);
    if ((tid&31)==0) reds[tid>>5] = sum;
    __syncthreads();
    sum = reds[0]+reds[1]+reds[2]+reds[3];
    float inv = 1.0f / sum;

    for (int t = tid; t < n; t += 128){
        float p = __expf(row[t] - mx) * inv;
        bf16 h,l; split2(p,h,l);
        ph[t]=h; pl[t]=l;
    }
    const int nend = ((s>>7)+1)<<7;
    for (int t = n + tid; t < nend; t += 128){ ph[t]=__float2bfloat16_rn(0.f); pl[t]=__float2bfloat16_rn(0.f); }
}

// ---------------- host side ----------------
static void launch_g(int BN, bool split,
    const bf16* Ah, const bf16* Al, const bf16* Bh, const bf16* Bl,
    float* Cf, bf16* Ch, bf16* Cl,
    int M, int N, int K, int lda, int ldb, int ldc,
    int Z, int zdiv,
    ll zA1, ll zA2, ll zB1, ll zB2, ll zC1, ll zC2,
    float alpha, bool causal, bool klimit)
{
    dim3 grid(N/BN, M/128, Z);
    int c = causal?1:0, kl = klimit?1:0;
    size_t sm = (size_t)NSTAGE * (2*128*64 + 2*(size_t)BN*64);
    if (BN == 128){
        if (split){
            cudaFuncSetAttribute(mma_gemm<128,true>, cudaFuncAttributeMaxDynamicSharedMemorySize, (int)sm);
            mma_gemm<128,true><<<grid,256,sm>>>(Ah,Al,Bh,Bl,Cf,Ch,Cl,K,lda,ldb,ldc,zdiv,zA1,zA2,zB1,zB2,zC1,zC2,alpha,c,kl);
        } else {
            cudaFuncSetAttribute(mma_gemm<128,false>, cudaFuncAttributeMaxDynamicSharedMemorySize, (int)sm);
            mma_gemm<128,false><<<grid,256,sm>>>(Ah,Al,Bh,Bl,Cf,Ch,Cl,K,lda,ldb,ldc,zdiv,zA1,zA2,zB1,zB2,zC1,zC2,alpha,c,kl);
        }
    } else {
        cudaFuncSetAttribute(mma_gemm<64,true>, cudaFuncAttributeMaxDynamicSharedMemorySize, (int)sm);
        mma_gemm<64,true><<<grid,256,sm>>>(Ah,Al,Bh,Bl,Cf,Ch,Cl,K,lda,ldb,ldc,zdiv,zA1,zA2,zB1,zB2,zC1,zC2,alpha,c,kl);
    }
}

#define SYM(p, s) cudaGetSymbolAddress((void**)&p, s)

extern "C" void kernel_launch(void* const* d_in, const int* in_sizes, int n_in,
                              void* d_out, int out_size)
{
    (void)in_sizes; (void)n_in; (void)out_size;
    const float* x      = (const float*)d_in[0];
    const float* angles = (const float*)d_in[1];
    const float* wq     = (const float*)d_in[2];
    const float* wkv_a  = (const float*)d_in[3];
    const float* wkv_b  = (const float*)d_in[4];
    const float* wo     = (const float*)d_in[5];
    const float* kvw    = (const float*)d_in[6];
    float* out = (float*)d_out;

    bf16 *xsh,*xsl,*wqh,*wql,*wah,*wal,*wbh,*wbl,*wbTh,*wbTl,*woh,*wol;
    bf16 *qsh,*qsl,*keh,*kel,*keTh,*keTl,*qeh,*qel,*prh,*prl,*olh,*oll,*osh,*osl,*kvh,*kvl;
    float *sc;
    SYM(xsh,g_xs_h); SYM(xsl,g_xs_l); SYM(wqh,g_wqs_h); SYM(wql,g_wqs_l);
    SYM(wah,g_was_h); SYM(wal,g_was_l); SYM(wbh,g_wbs_h); SYM(wbl,g_wbs_l);
    SYM(wbTh,g_wbT_h); SYM(wbTl,g_wbT_l); SYM(woh,g_wos_h); SYM(wol,g_wos_l);
    SYM(qsh,g_qs_h); SYM(qsl,g_qs_l); SYM(kvh,g_kvs_h); SYM(kvl,g_kvs_l);
    SYM(keh,g_ke_h); SYM(kel,g_ke_l); SYM(keTh,g_keT_h); SYM(keTl,g_keT_l);
    SYM(qeh,g_qe_h); SYM(qel,g_qe_l); SYM(prh,g_pr_h); SYM(prl,g_pr_l);
    SYM(olh,g_ol_h); SYM(oll,g_ol_l); SYM(osh,g_os_h); SYM(osl,g_os_l);
    SYM(sc,g_scores);

    const double msc = 0.1*log(40.0) + 1.0;
    const float softmax_scale = (float)(pow((double)QD, -0.5)*msc*msc);

    // 0) split inputs into bf16 hi/lo planes
    {
        int n;
        n = NTOK*DIM/4;            split_arr<<<(n+255)/256,256>>>((const float4*)x, xsh, xsl, n);
        n = QOUT*DIM/4;            split_arr<<<(n+255)/256,256>>>((const float4*)wq, wqh, wql, n);
        n = KVOUT*DIM/4;           split_arr<<<(n+255)/256,256>>>((const float4*)wkv_a, wah, wal, n);
        n = NH*(NOPE+VDIM)*KVR/4;  split_arr<<<(n+255)/256,256>>>((const float4*)wkv_b, wbh, wbl, n);
        n = DIM*NH*VDIM/4;         split_arr<<<(n+255)/256,256>>>((const float4*)wo, woh, wol, n);
        n = NH*KVR*NOPE;           splitT_wkvb<<<(n+255)/256,256>>>(wkv_b);
    }
    rope_prep_kernel<<<(S_LEN*RHALF+127)/128, 128>>>(angles);

    // 1) q = x @ wq^T
    launch_g(128,true, xsh,xsl, wqh,wql, 0, qsh,qsl,
             NTOK, QOUT, DIM, DIM, DIM, QOUT, 1,1, 0,0,0,0,0,0, 1.f,false,false);

    // 2) kv = x @ wkv_a^T  (512 + 64)
    launch_g(128,true, xsh,xsl, wah,wal, 0, kvh,kvl,
             NTOK, 512, DIM, DIM, DIM, KVOUT, 1,1, 0,0,0,0,0,0, 1.f,false,false);
    launch_g(64,true, xsh,xsl, wah+(size_t)512*DIM, wal+(size_t)512*DIM, 0, kvh+512, kvl+512,
             NTOK, 64, DIM, DIM, DIM, KVOUT, 1,1, 0,0,0,0,0,0, 1.f,false,false);

    // 3) keff planes (+ transposed copy)
    prep_keff_kernel<<<NTOK, 128>>>(kvw);

    // 4) rope(q_pe) -> qeff[...,512:576]
    prep_qpe_kernel<<<dim3(NTOK, NH), 32>>>();

    // 5) qeff[...,0:512] = q_nope @ wkv_bT  (per (b,h))
    launch_g(128,true, qsh,qsl, wbTh,wbTl, 0, qeh,qel,
             S_LEN, KVR, NOPE, QOUT, NOPE, DEFF, BATCH*NH, NH,
             (ll)QD, (ll)S_LEN*QOUT, (ll)KVR*NOPE, 0,
             (ll)S_LEN*DEFF, (ll)NH*S_LEN*DEFF, 1.f,false,false);

    // 6) scores = scale * qeff @ keff^T  (causal block-skip)
    launch_g(128,false, qeh,qel, keh,kel, sc, 0,0,
             S_LEN, S_LEN, DEFF, DEFF, DEFF, S_LEN, BATCH*NH, NH,
             (ll)S_LEN*DEFF, (ll)NH*S_LEN*DEFF, 0, (ll)S_LEN*DEFF,
             (ll)S_LEN*S_LEN, (ll)NH*S_LEN*S_LEN, softmax_scale, true, false);

    // 7) softmax -> probs planes
    softmax_kernel<<<dim3(S_LEN, BATCH*NH), 128>>>();

    // 8) olat = probs @ keffT^T  (K causally capped)
    launch_g(128,true, prh,prl, keTh,keTl, 0, olh,oll,
             S_LEN, KVR, S_LEN, S_LEN, S_LEN, KVR, BATCH*NH, NH,
             (ll)S_LEN*S_LEN, (ll)NH*S_LEN*S_LEN, 0, (ll)DEFF*S_LEN,
             (ll)S_LEN*KVR, (ll)NH*S_LEN*KVR, 1.f, false, true);

    // 9) o[:, h*128:(h+1)*128] = olat_h @ wkv_b_v^T
    launch_g(128,true, olh,oll, wbh+(size_t)NOPE*KVR, wbl+(size_t)NOPE*KVR, 0, osh,osl,
             S_LEN, VDIM, KVR, KVR, KVR, NH*VDIM, BATCH*NH, NH,
             (ll)S_LEN*KVR, (ll)NH*S_LEN*KVR, (ll)(NOPE+VDIM)*KVR, 0,
             (ll)VDIM, (ll)S_LEN*NH*VDIM, 1.f, false, false);

    // 10) out = o @ wo^T  (fp32 output)
    launch_g(128,false, osh,osl, woh,wol, out, 0,0,
             NTOK, DIM, NH*VDIM, NH*VDIM, NH*VDIM, DIM, 1,1,
             0,0,0,0,0,0, 1.f,false,false);
}

// round 5
// speedup vs baseline: 1.1973x; 1.1973x over previous
#include <cuda_runtime.h>
#include <cuda_bf16.h>
#include <math.h>
#include <stdint.h>

// ---------------- problem constants ----------------
#define S_LEN 2048
#define BATCH 2
#define NTOK  (S_LEN*BATCH)     // 4096
#define NH    16
#define DIM   2048
#define NOPE  128
#define ROPE  64
#define RHALF 32
#define VDIM  128
#define KVR   512
#define QD    (NOPE+ROPE)       // 192
#define QOUT  (NH*QD)           // 3072
#define KVOUT (KVR+ROPE)        // 576
#define DEFF  576
#define NSTAGE 3
#define LOG2E 1.4426950408889634

typedef long long ll;
typedef __nv_bfloat16 bf16;
typedef __nv_bfloat162 bf162;

// ---------------- scratch: bf16 hi/lo planes + fp32 scores ----------------
__device__ __align__(16) bf16 g_xs_h [(size_t)NTOK*DIM],    g_xs_l [(size_t)NTOK*DIM];
__device__ __align__(16) bf16 g_wqs_h[(size_t)QOUT*DIM],    g_wqs_l[(size_t)QOUT*DIM];
__device__ __align__(16) bf16 g_was_h[(size_t)KVOUT*DIM],   g_was_l[(size_t)KVOUT*DIM];
__device__ __align__(16) bf16 g_wbs_h[(size_t)NH*(NOPE+VDIM)*KVR], g_wbs_l[(size_t)NH*(NOPE+VDIM)*KVR];
__device__ __align__(16) bf16 g_wbT_h[(size_t)NH*KVR*NOPE], g_wbT_l[(size_t)NH*KVR*NOPE];
__device__ __align__(16) bf16 g_wos_h[(size_t)DIM*NH*VDIM], g_wos_l[(size_t)DIM*NH*VDIM];
__device__ __align__(16) bf16 g_qs_h [(size_t)NTOK*QOUT],   g_qs_l [(size_t)NTOK*QOUT];
__device__ __align__(16) bf16 g_kvs_h[(size_t)NTOK*KVOUT],  g_kvs_l[(size_t)NTOK*KVOUT];
__device__ __align__(16) bf16 g_ke_h [(size_t)NTOK*DEFF],   g_ke_l [(size_t)NTOK*DEFF];
__device__ __align__(16) bf16 g_keT_h[(size_t)BATCH*DEFF*S_LEN], g_keT_l[(size_t)BATCH*DEFF*S_LEN];
__device__ __align__(16) bf16 g_qe_h [(size_t)BATCH*NH*S_LEN*DEFF], g_qe_l [(size_t)BATCH*NH*S_LEN*DEFF];
__device__ float g_scores[(size_t)BATCH*NH*S_LEN*S_LEN];
__device__ __align__(16) bf16 g_pr_h [(size_t)BATCH*NH*S_LEN*S_LEN], g_pr_l [(size_t)BATCH*NH*S_LEN*S_LEN];
__device__ __align__(16) bf16 g_ol_h [(size_t)BATCH*NH*S_LEN*KVR],  g_ol_l [(size_t)BATCH*NH*S_LEN*KVR];
__device__ __align__(16) bf16 g_os_h [(size_t)NTOK*NH*VDIM], g_os_l [(size_t)NTOK*NH*VDIM];
__device__ float g_cos[S_LEN*RHALF];
__device__ float g_sin[S_LEN*RHALF];

// ---------------- helpers ----------------
__device__ __forceinline__ float warpMax(float v){
    #pragma unroll
    for (int o=16;o;o>>=1) v = fmaxf(v, __shfl_xor_sync(0xffffffffu, v, o));
    return v;
}
__device__ __forceinline__ float warpSum(float v){
    #pragma unroll
    for (int o=16;o;o>>=1) v += __shfl_xor_sync(0xffffffffu, v, o);
    return v;
}
__device__ __forceinline__ uint32_t smem_u32(const void* p){
    uint32_t a;
    asm("{ .reg .u64 t; cvta.to.shared.u64 t, %1; cvt.u32.u64 %0, t; }" : "=r"(a) : "l"(p));
    return a;
}
__device__ __forceinline__ void split2(float f, bf16& h, bf16& l){
    h = __float2bfloat16_rn(f);
    l = __float2bfloat16_rn(f - __bfloat162float(h));
}
__device__ __forceinline__ float rejoin(bf16 h, bf16 l){
    return __bfloat162float(h) + __bfloat162float(l);
}
__device__ __forceinline__ void mma_bf16(float* d, const uint32_t* a, const uint32_t* b){
    asm volatile(
        "mma.sync.aligned.m16n8k16.row.col.f32.bf16.bf16.f32 "
        "{%0,%1,%2,%3}, {%4,%5,%6,%7}, {%8,%9}, {%0,%1,%2,%3};"
        : "+f"(d[0]), "+f"(d[1]), "+f"(d[2]), "+f"(d[3])
        : "r"(a[0]), "r"(a[1]), "r"(a[2]), "r"(a[3]), "r"(b[0]), "r"(b[1]));
}
__device__ __forceinline__ void ldsm4(uint32_t* r, uint32_t a){
    asm volatile("ldmatrix.sync.aligned.m8n8.x4.shared.b16 {%0,%1,%2,%3}, [%4];"
        : "=r"(r[0]), "=r"(r[1]), "=r"(r[2]), "=r"(r[3]) : "r"(a));
}
__device__ __forceinline__ void cp16(uint32_t dst, const void* src){
    asm volatile("cp.async.cg.shared.global [%0], [%1], 16;\n" :: "r"(dst), "l"(src) : "memory");
}
__device__ __forceinline__ void cp_commit(){ asm volatile("cp.async.commit_group;\n" ::: "memory"); }
__device__ __forceinline__ void cp_wait1(){ asm volatile("cp.async.wait_group 1;\n" ::: "memory"); }

// swizzle for 64B rows: XOR bits[5:4] with bits[8:7]
__device__ __forceinline__ uint32_t swz(uint32_t o){ return o ^ ((o>>3)&0x30u); }

// ---------------- split kernels ----------------
__global__ void split_arr(const float4* __restrict__ src, bf16* __restrict__ h, bf16* __restrict__ l, int n4){
    int i = blockIdx.x*blockDim.x + threadIdx.x;
    if (i >= n4) return;
    float4 v = src[i];
    bf16 h0,l0,h1,l1,h2,l2,h3,l3;
    split2(v.x,h0,l0); split2(v.y,h1,l1); split2(v.z,h2,l2); split2(v.w,h3,l3);
    bf162* hp = (bf162*)(h + 4*(size_t)i);
    bf162* lp = (bf162*)(l + 4*(size_t)i);
    bf162 a; a.x=h0; a.y=h1; hp[0]=a;
    bf162 b; b.x=h2; b.y=h3; hp[1]=b;
    bf162 c; c.x=l0; c.y=l1; lp[0]=c;
    bf162 d; d.x=l2; d.y=l3; lp[1]=d;
}
__global__ void splitT_wkvb(const float* __restrict__ wb){
    int i = blockIdx.x*blockDim.x + threadIdx.x;
    if (i >= NH*KVR*NOPE) return;
    int d = i % NOPE, c = (i/NOPE) % KVR, h = i/(NOPE*KVR);
    float v = wb[((size_t)h*(NOPE+VDIM) + d)*KVR + c];
    split2(v, g_wbT_h[i], g_wbT_l[i]);
}

// ---------------- prep kernels ----------------
__global__ void rope_prep_kernel(const float* __restrict__ ang){
    int i = blockIdx.x*blockDim.x + threadIdx.x;
    if (i < S_LEN*RHALF){
        float a = ang[i];
        g_cos[i] = cosf(a);
        g_sin[i] = sinf(a);
    }
}

__global__ void prep_keff_kernel(const float* __restrict__ kvw){
    int t = blockIdx.x;
    int b = t / S_LEN, s = t % S_LEN;
    int tid = threadIdx.x;
    float v[4];
    #pragma unroll
    for (int j=0;j<4;j++){
        size_t idx = (size_t)t*KVOUT + 4*tid + j;
        v[j] = rejoin(g_kvs_h[idx], g_kvs_l[idx]);
    }
    float ss = v[0]*v[0]+v[1]*v[1]+v[2]*v[2]+v[3]*v[3];
    ss = warpSum(ss);
    __shared__ float red[4];
    if ((tid&31)==0) red[tid>>5] = ss;
    __syncthreads();
    float tot = red[0]+red[1]+red[2]+red[3];
    float r = rsqrtf(tot*(1.0f/KVR) + 1e-6f);
    #pragma unroll
    for (int j=0;j<4;j++){
        int c = 4*tid + j;
        float o = v[j]*r*kvw[c];
        bf16 h,l; split2(o,h,l);
        size_t di = (size_t)t*DEFF + c;
        g_ke_h[di]=h; g_ke_l[di]=l;
        size_t ti = ((size_t)b*DEFF + c)*S_LEN + s;
        g_keT_h[ti]=h; g_keT_l[ti]=l;
    }
    if (tid < RHALF){
        size_t pi = (size_t)t*KVOUT + KVR + 2*tid;
        float xr = rejoin(g_kvs_h[pi],   g_kvs_l[pi]);
        float xi = rejoin(g_kvs_h[pi+1], g_kvs_l[pi+1]);
        float c  = g_cos[s*RHALF+tid], sn = g_sin[s*RHALF+tid];
        float yr = xr*c - xi*sn, yi = xr*sn + xi*c;
        bf16 hr,lr,hi2,li; split2(yr,hr,lr); split2(yi,hi2,li);
        size_t di = (size_t)t*DEFF + KVR + 2*tid;
        g_ke_h[di]=hr; g_ke_l[di]=lr; g_ke_h[di+1]=hi2; g_ke_l[di+1]=li;
        size_t t0 = ((size_t)b*DEFF + KVR + 2*tid)*S_LEN + s;
        size_t t1 = ((size_t)b*DEFF + KVR + 2*tid + 1)*S_LEN + s;
        g_keT_h[t0]=hr; g_keT_l[t0]=lr; g_keT_h[t1]=hi2; g_keT_l[t1]=li;
    }
}

__global__ void prep_qpe_kernel(){
    int t = blockIdx.x, h = blockIdx.y;
    int b = t / S_LEN, s = t % S_LEN;
    int i = threadIdx.x;   // 0..31
    size_t si = (size_t)t*QOUT + h*QD + NOPE + 2*i;
    float xr = rejoin(g_qs_h[si],   g_qs_l[si]);
    float xi = rejoin(g_qs_h[si+1], g_qs_l[si+1]);
    float c  = g_cos[s*RHALF+i], sn = g_sin[s*RHALF+i];
    float yr = xr*c - xi*sn, yi = xr*sn + xi*c;
    size_t di = ((size_t)(b*NH+h)*S_LEN + s)*DEFF + KVR + 2*i;
    bf16 hh,ll_; split2(yr,hh,ll_); g_qe_h[di]=hh;   g_qe_l[di]=ll_;
    split2(yi,hh,ll_);              g_qe_h[di+1]=hh; g_qe_l[di+1]=ll_;
}

// ---------------- bf16x3 split GEMM with ldmatrix ----------------
// C = alpha * (Ah+Al)[M,K] @ (Bh+Bl)[N,K]^T   (operands K-contiguous)
template<int BN_T, bool SPLIT_OUT>
__global__ __launch_bounds__(256,2) void mma_gemm(
    const bf16* __restrict__ Ah, const bf16* __restrict__ Al,
    const bf16* __restrict__ Bh, const bf16* __restrict__ Bl,
    float* __restrict__ Cf, bf16* __restrict__ Ch, bf16* __restrict__ Cl,
    int K, int lda, int ldb, int ldc, int zdiv,
    ll zA1, ll zA2, ll zB1, ll zB2, ll zC1, ll zC2,
    float alpha, int causal, int klimit)
{
    if (causal && blockIdx.x > blockIdx.y) return;
    constexpr int WN  = BN_T/32;
    constexpr int WM  = 8/WN;
    constexpr int WTM = 128/WM;
    constexpr int MF  = WTM/16;
    constexpr int NF  = 4;
    constexpr int SA  = 128*64;        // 8KB per A plane
    constexpr int SB  = BN_T*64;
    constexpr int STG = 2*SA + 2*SB;

    extern __shared__ char smc[];
    const uint32_t sbase = smem_u32(smc);

    const int tid = threadIdx.x, lane = tid & 31, wid = tid >> 5;
    const int wm = wid / WN, wn = wid % WN;
    const int grp = lane >> 2, tig = lane & 3;
    const int lrow = lane & 7, sub = lane >> 3;
    const int zl = blockIdx.z % zdiv, zh = blockIdx.z / zdiv;
    const ll n0 = (ll)blockIdx.x * BN_T;

    // ldmatrix lane address components
    const int aRowB = wm*WTM + ((sub&1)<<3) + lrow;  // + mf*16
    const int aKo   = (sub>>1)<<4;                   // + ck
    const int bRowB = wn*32 + ((sub>>1)<<3) + lrow;  // + nfp*16
    const int bKo   = (sub&1)<<4;                    // + ck

    const ll aoff = zl*zA1 + zh*zA2 + (ll)blockIdx.y*128*lda;
    const bf16* Ahb = Ah + aoff;
    const bf16* Alb = Al + aoff;
    const ll boff = zl*zB1 + zh*zB2 + n0*ldb;
    const bf16* Bhb = Bh + boff;
    const bf16* Blb = Bl + boff;

    int kEnd = K;
    if (klimit){ int kl = ((int)blockIdx.y + 1)*128; if (kl < kEnd) kEnd = kl; }
    const int nk = kEnd >> 5;

    float acc[MF][NF][4];
    #pragma unroll
    for (int i=0;i<MF;i++)
        #pragma unroll
        for (int j=0;j<NF;j++)
            #pragma unroll
            for (int c=0;c<4;c++) acc[i][j][c] = 0.f;

    const int row = tid >> 2, g = tid & 3;

    auto LOAD = [&](int kb){
        const int s = kb % NSTAGE;
        const uint32_t ub = sbase + (uint32_t)(s*STG);
        const ll koff = ((ll)kb << 5) + g*8;
        #pragma unroll
        for (int i=0;i<2;i++){
            int r = row + i*64;
            uint32_t o = swz((uint32_t)(r*64 + g*16));
            cp16(ub + o,      Ahb + (ll)r*lda + koff);
            cp16(ub + SA + o, Alb + (ll)r*lda + koff);
        }
        #pragma unroll
        for (int i=0;i<BN_T/64;i++){
            int r = row + i*64;
            uint32_t o = swz((uint32_t)(r*64 + g*16));
            cp16(ub + 2*SA + o,      Bhb + (ll)r*ldb + koff);
            cp16(ub + 2*SA + SB + o, Blb + (ll)r*ldb + koff);
        }
        cp_commit();
    };

    #pragma unroll
    for (int kb=0; kb<NSTAGE-1; kb++) if (kb < nk) LOAD(kb);

    for (int k=0; k<nk; k++){
        cp_wait1();
        __syncthreads();
        if (k + NSTAGE - 1 < nk) LOAD(k + NSTAGE - 1);
        else cp_commit();

        const int s = k % NSTAGE;
        const uint32_t AH = sbase + (uint32_t)(s*STG);
        const uint32_t AL = AH + SA;
        const uint32_t BH = AH + 2*SA;
        const uint32_t BL = BH + SB;

        #pragma unroll
        for (int kk=0; kk<2; kk++){
            const int ck = kk*32;
            uint32_t bh[8], bl[8];
            #pragma unroll
            for (int nfp=0; nfp<2; nfp++){
                uint32_t bo = swz((uint32_t)((bRowB + nfp*16)*64 + ck + bKo));
                ldsm4(&bh[4*nfp], BH + bo);
                ldsm4(&bl[4*nfp], BL + bo);
            }
            #pragma unroll
            for (int mf=0; mf<MF; mf++){
                uint32_t ao = swz((uint32_t)((aRowB + mf*16)*64 + ck + aKo));
                uint32_t ah[4], al[4];
                ldsm4(ah, AH + ao);
                ldsm4(al, AL + ao);
                #pragma unroll
                for (int nf=0; nf<NF; nf++) mma_bf16(acc[mf][nf], ah, &bh[2*nf]);
                #pragma unroll
                for (int nf=0; nf<NF; nf++) mma_bf16(acc[mf][nf], ah, &bl[2*nf]);
                #pragma unroll
                for (int nf=0; nf<NF; nf++) mma_bf16(acc[mf][nf], al, &bh[2*nf]);
            }
        }
    }

    // ---- epilogue ----
    const ll cbase = zl*zC1 + zh*zC2
                   + ((ll)blockIdx.y*128 + wm*WTM)*ldc + n0 + wn*32;
    #pragma unroll
    for (int mf=0; mf<MF; mf++){
        int r0 = mf*16 + grp;
        #pragma unroll
        for (int nf=0; nf<NF; nf++){
            int c = nf*8 + tig*2;
            #pragma unroll
            for (int half=0; half<2; half++){
                ll off = cbase + (ll)(r0 + half*8)*ldc + c;
                float v0 = acc[mf][nf][2*half+0]*alpha;
                float v1 = acc[mf][nf][2*half+1]*alpha;
                if (SPLIT_OUT){
                    bf16 h0,l0,h1,l1;
                    split2(v0,h0,l0); split2(v1,h1,l1);
                    bf162 hp; hp.x=h0; hp.y=h1;
                    bf162 lp; lp.x=l0; lp.y=l1;
                    *(bf162*)(Ch + off) = hp;
                    *(bf162*)(Cl + off) = lp;
                } else {
                    float2 o; o.x=v0; o.y=v1;
                    *(float2*)(Cf + off) = o;
                }
            }
        }
    }
}

// ---------------- causal softmax (single global read, single exp pass) ----------------
// scores are pre-scaled by softmax_scale*LOG2E, so probs = exp2(s - max).
__global__ void softmax_kernel(){
    const int s = blockIdx.x;
    const ll z = blockIdx.y;
    const float* row = g_scores + (z*S_LEN + (ll)s)*S_LEN;
    bf16* ph = g_pr_h + (z*S_LEN + (ll)s)*S_LEN;
    bf16* pl = g_pr_l + (z*S_LEN + (ll)s)*S_LEN;
    const int n = s + 1;
    const int nend = ((s>>7)+1)<<7;   // 128-aligned (PV reads whole blocks)
    const int tid = threadIdx.x;

    float e[16];
    float mx = -1e30f;
    #pragma unroll
    for (int i=0;i<16;i++){
        int t = tid + i*128;
        e[i] = (t < n) ? row[t] : -1e30f;
        mx = fmaxf(mx, e[i]);
    }
    mx = warpMax(mx);
    __shared__ float redm[4], reds[4];
    if ((tid&31)==0) redm[tid>>5] = mx;
    __syncthreads();
    mx = fmaxf(fmaxf(redm[0],redm[1]), fmaxf(redm[2],redm[3]));

    float sum = 0.f;
    #pragma unroll
    for (int i=0;i<16;i++){
        int t = tid + i*128;
        float v = (t < n) ? exp2f(e[i] - mx) : 0.f;
        e[i] = v;
        sum += v;
    }
    sum = warpSum(sum);
    if ((tid&31)==0) reds[tid>>5] = sum;
    __syncthreads();
    sum = reds[0]+reds[1]+reds[2]+reds[3];
    const float inv = 1.0f / sum;

    #pragma unroll
    for (int i=0;i<16;i++){
        int t = tid + i*128;
        if (t < nend){
            float p = e[i]*inv;
            bf16 h,l; split2(p,h,l);
            ph[t]=h; pl[t]=l;
        }
    }
}

// ---------------- host side ----------------
static void launch_g(int BN, bool split,
    const bf16* Ah, const bf16* Al, const bf16* Bh, const bf16* Bl,
    float* Cf, bf16* Ch, bf16* Cl,
    int M, int N, int K, int lda, int ldb, int ldc,
    int Z, int zdiv,
    ll zA1, ll zA2, ll zB1, ll zB2, ll zC1, ll zC2,
    float alpha, bool causal, bool klimit)
{
    dim3 grid(N/BN, M/128, Z);
    int c = causal?1:0, kl = klimit?1:0;
    size_t sm = (size_t)NSTAGE * (2*128*64 + 2*(size_t)BN*64);
    if (BN == 128){
        if (split){
            cudaFuncSetAttribute(mma_gemm<128,true>, cudaFuncAttributeMaxDynamicSharedMemorySize, (int)sm);
            mma_gemm<128,true><<<grid,256,sm>>>(Ah,Al,Bh,Bl,Cf,Ch,Cl,K,lda,ldb,ldc,zdiv,zA1,zA2,zB1,zB2,zC1,zC2,alpha,c,kl);
        } else {
            cudaFuncSetAttribute(mma_gemm<128,false>, cudaFuncAttributeMaxDynamicSharedMemorySize, (int)sm);
            mma_gemm<128,false><<<grid,256,sm>>>(Ah,Al,Bh,Bl,Cf,Ch,Cl,K,lda,ldb,ldc,zdiv,zA1,zA2,zB1,zB2,zC1,zC2,alpha,c,kl);
        }
    } else {
        cudaFuncSetAttribute(mma_gemm<64,true>, cudaFuncAttributeMaxDynamicSharedMemorySize, (int)sm);
        mma_gemm<64,true><<<grid,256,sm>>>(Ah,Al,Bh,Bl,Cf,Ch,Cl,K,lda,ldb,ldc,zdiv,zA1,zA2,zB1,zB2,zC1,zC2,alpha,c,kl);
    }
}

#define SYM(p, s) cudaGetSymbolAddress((void**)&p, s)

extern "C" void kernel_launch(void* const* d_in, const int* in_sizes, int n_in,
                              void* d_out, int out_size)
{
    (void)in_sizes; (void)n_in; (void)out_size;
    const float* x      = (const float*)d_in[0];
    const float* angles = (const float*)d_in[1];
    const float* wq     = (const float*)d_in[2];
    const float* wkv_a  = (const float*)d_in[3];
    const float* wkv_b  = (const float*)d_in[4];
    const float* wo     = (const float*)d_in[5];
    const float* kvw    = (const float*)d_in[6];
    float* out = (float*)d_out;

    bf16 *xsh,*xsl,*wqh,*wql,*wah,*wal,*wbh,*wbl,*wbTh,*wbTl,*woh,*wol;
    bf16 *qsh,*qsl,*keh,*kel,*keTh,*keTl,*qeh,*qel,*prh,*prl,*olh,*oll,*osh,*osl,*kvh,*kvl;
    float *sc;
    SYM(xsh,g_xs_h); SYM(xsl,g_xs_l); SYM(wqh,g_wqs_h); SYM(wql,g_wqs_l);
    SYM(wah,g_was_h); SYM(wal,g_was_l); SYM(wbh,g_wbs_h); SYM(wbl,g_wbs_l);
    SYM(wbTh,g_wbT_h); SYM(wbTl,g_wbT_l); SYM(woh,g_wos_h); SYM(wol,g_wos_l);
    SYM(qsh,g_qs_h); SYM(qsl,g_qs_l); SYM(kvh,g_kvs_h); SYM(kvl,g_kvs_l);
    SYM(keh,g_ke_h); SYM(kel,g_ke_l); SYM(keTh,g_keT_h); SYM(keTl,g_keT_l);
    SYM(qeh,g_qe_h); SYM(qel,g_qe_l); SYM(prh,g_pr_h); SYM(prl,g_pr_l);
    SYM(olh,g_ol_h); SYM(oll,g_ol_l); SYM(osh,g_os_h); SYM(osl,g_os_l);
    SYM(sc,g_scores);

    const double msc = 0.1*log(40.0) + 1.0;
    const float softmax_scale = (float)(pow((double)QD, -0.5)*msc*msc);
    const float score_alpha = (float)((double)softmax_scale * LOG2E);

    // 0) split inputs into bf16 hi/lo planes
    {
        int n;
        n = NTOK*DIM/4;            split_arr<<<(n+255)/256,256>>>((const float4*)x, xsh, xsl, n);
        n = QOUT*DIM/4;            split_arr<<<(n+255)/256,256>>>((const float4*)wq, wqh, wql, n);
        n = KVOUT*DIM/4;           split_arr<<<(n+255)/256,256>>>((const float4*)wkv_a, wah, wal, n);
        n = NH*(NOPE+VDIM)*KVR/4;  split_arr<<<(n+255)/256,256>>>((const float4*)wkv_b, wbh, wbl, n);
        n = DIM*NH*VDIM/4;         split_arr<<<(n+255)/256,256>>>((const float4*)wo, woh, wol, n);
        n = NH*KVR*NOPE;           splitT_wkvb<<<(n+255)/256,256>>>(wkv_b);
    }
    rope_prep_kernel<<<(S_LEN*RHALF+127)/128, 128>>>(angles);

    // 1) q = x @ wq^T
    launch_g(128,true, xsh,xsl, wqh,wql, 0, qsh,qsl,
             NTOK, QOUT, DIM, DIM, DIM, QOUT, 1,1, 0,0,0,0,0,0, 1.f,false,false);

    // 2) kv = x @ wkv_a^T  (512 + 64)
    launch_g(128,true, xsh,xsl, wah,wal, 0, kvh,kvl,
             NTOK, 512, DIM, DIM, DIM, KVOUT, 1,1, 0,0,0,0,0,0, 1.f,false,false);
    launch_g(64,true, xsh,xsl, wah+(size_t)512*DIM, wal+(size_t)512*DIM, 0, kvh+512, kvl+512,
             NTOK, 64, DIM, DIM, DIM, KVOUT, 1,1, 0,0,0,0,0,0, 1.f,false,false);

    // 3) keff planes (+ transposed copy)
    prep_keff_kernel<<<NTOK, 128>>>(kvw);

    // 4) rope(q_pe) -> qeff[...,512:576]
    prep_qpe_kernel<<<dim3(NTOK, NH), 32>>>();

    // 5) qeff[...,0:512] = q_nope @ wkv_bT  (per (b,h))
    launch_g(128,true, qsh,qsl, wbTh,wbTl, 0, qeh,qel,
             S_LEN, KVR, NOPE, QOUT, NOPE, DEFF, BATCH*NH, NH,
             (ll)QD, (ll)S_LEN*QOUT, (ll)KVR*NOPE, 0,
             (ll)S_LEN*DEFF, (ll)NH*S_LEN*DEFF, 1.f,false,false);

    // 6) scores = scale*log2e * qeff @ keff^T  (causal block-skip)
    launch_g(128,false, qeh,qel, keh,kel, sc, 0,0,
             S_LEN, S_LEN, DEFF, DEFF, DEFF, S_LEN, BATCH*NH, NH,
             (ll)S_LEN*DEFF, (ll)NH*S_LEN*DEFF, 0, (ll)S_LEN*DEFF,
             (ll)S_LEN*S_LEN, (ll)NH*S_LEN*S_LEN, score_alpha, true, false);

    // 7) softmax -> probs planes
    softmax_kernel<<<dim3(S_LEN, BATCH*NH), 128>>>();

    // 8) olat = probs @ keffT^T  (K causally capped)
    launch_g(128,true, prh,prl, keTh,keTl, 0, olh,oll,
             S_LEN, KVR, S_LEN, S_LEN, S_LEN, KVR, BATCH*NH, NH,
             (ll)S_LEN*S_LEN, (ll)NH*S_LEN*S_LEN, 0, (ll)DEFF*S_LEN,
             (ll)S_LEN*KVR, (ll)NH*S_LEN*KVR, 1.f, false, true);

    // 9) o[:, h*128:(h+1)*128] = olat_h @ wkv_b_v^T
    launch_g(128,true, olh,oll, wbh+(size_t)NOPE*KVR, wbl+(size_t)NOPE*KVR, 0, osh,osl,
             S_LEN, VDIM, KVR, KVR, KVR, NH*VDIM, BATCH*NH, NH,
             (ll)S_LEN*KVR, (ll)NH*S_LEN*KVR, (ll)(NOPE+VDIM)*KVR, 0,
             (ll)VDIM, (ll)S_LEN*NH*VDIM, 1.f, false, false);

    // 10) out = o @ wo^T  (fp32 output)
    launch_g(128,false, osh,osl, woh,wol, out, 0,0,
             NTOK, DIM, NH*VDIM, NH*VDIM, NH*VDIM, DIM, 1,1,
             0,0,0,0,0,0, 1.f,false,false);
}